// round 1
// baseline (speedup 1.0000x reference)
#include <cuda_runtime.h>
#include <cuda_bf16.h>
#include <math.h>
#include <stdint.h>

// Problem constants (fixed shapes)
#define B_N 2048
#define D_N 512
#define H_N 512
#define A_N 18
#define T_N 16

// ---------------- device scratch (no allocation allowed) ----------------
__device__ int   g_offsets[T_N + 1];
__device__ int   g_rowmap[B_N];          // sorted-by-task original row indices
__device__ float g_h[(size_t)B_N * H_N]; // hidden activations, SORTED order (4 MB)

// ---------------- f32x2 helpers (sm_100+ packed fp32) ----------------
__device__ __forceinline__ unsigned long long fma_f32x2(unsigned long long a,
                                                        unsigned long long b,
                                                        unsigned long long c) {
    unsigned long long d;
    asm("fma.rn.f32x2 %0, %1, %2, %3;" : "=l"(d) : "l"(a), "l"(b), "l"(c));
    return d;
}
__device__ __forceinline__ unsigned long long pack2(float x, float y) {
    unsigned long long r;
    asm("mov.b64 %0, {%1, %2};" : "=l"(r) : "f"(x), "f"(y));
    return r;
}
__device__ __forceinline__ float2 unpack2(unsigned long long v) {
    float2 r;
    asm("mov.b64 {%0, %1}, %2;" : "=f"(r.x), "=f"(r.y) : "l"(v));
    return r;
}

// ---------------- kernel 1: group rows by task ----------------
// Single block: histogram -> scan -> scatter. Deterministic outputs downstream
// (per-row math is independent of slot order within a task).
__global__ void group_kernel(const int* __restrict__ task_id) {
    __shared__ int scnt[T_N];
    __shared__ int soff[T_N + 1];
    __shared__ int scur[T_N];
    int tid = threadIdx.x;
    if (tid < T_N) { scnt[tid] = 0; scur[tid] = 0; }
    __syncthreads();
    for (int b = tid; b < B_N; b += blockDim.x)
        atomicAdd(&scnt[task_id[b]], 1);
    __syncthreads();
    if (tid == 0) {
        int acc = 0;
        for (int t = 0; t < T_N; t++) { soff[t] = acc; acc += scnt[t]; }
        soff[T_N] = acc;
    }
    __syncthreads();
    if (tid <= T_N) g_offsets[tid] = soff[tid];
    for (int b = tid; b < B_N; b += blockDim.x) {
        int t = task_id[b];
        int p = soff[t] + atomicAdd(&scur[t], 1);
        g_rowmap[p] = b;
    }
}

// ---------------- kernel 2: fused gathered GEMM (fc1) + bias + relu ----------------
// Tile: BM=64 rows x BN=128 cols, BK=16. 256 threads, each computes 8x4 outputs
// using packed fma.rn.f32x2 (2 MACs/op). h written in sorted order.
#define BM 64
#define BN 128
#define BK 16

__global__ __launch_bounds__(256, 2)
void fc1_kernel(const float* __restrict__ xs,
                const float* __restrict__ W1,
                const float* __restrict__ b1) {
    const int t = blockIdx.z;
    const int start = g_offsets[t];
    const int end   = g_offsets[t + 1];
    const int rowStart = start + blockIdx.x * BM;
    if (rowStart >= end) return;
    const int cBase = blockIdx.y * BN;

    __shared__ float Xs[BK][BM + 1];   // +1 pad: conflict-free transposed stores
    __shared__ float Ws[BK][BN];
    __shared__ int   srow[BM];

    const int tid = threadIdx.x;
    const int tx = tid & 31;           // 32 col-groups
    const int ty = tid >> 5;           // 8 row-groups

    // cache gathered row indices (clamp tail to a valid row)
    if (tid < BM) {
        int p = rowStart + tid;
        srow[tid] = g_rowmap[(p < end) ? p : rowStart];
    }
    __syncthreads();

    // loader indices
    const int wrow = tid >> 4;               // 0..15
    const int wq   = tid & 15;               // two float4s per thread per row
    const int xrow = tid >> 2;               // 0..63
    const int xq   = tid & 3;                // float4 within 16-wide k chunk

    const float* __restrict__ Wg =
        W1 + ((size_t)t * D_N) * H_N + cBase;

    // prefetch tile 0 into registers
    float4 wa, wb, xr;
    {
        const float* wp = Wg + (size_t)wrow * H_N;
        wa = *(const float4*)(wp + wq * 4);
        wb = *(const float4*)(wp + (wq + 16) * 4);
        const float* xp = xs + (size_t)srow[xrow] * D_N + xq * 4;
        xr = *(const float4*)xp;
    }

    unsigned long long acc[8][2];
    unsigned long long z = pack2(0.f, 0.f);
#pragma unroll
    for (int i = 0; i < 8; i++) { acc[i][0] = z; acc[i][1] = z; }

    const int NKT = D_N / BK; // 32
    for (int kt = 0; kt < NKT; kt++) {
        // commit staged regs to smem
        Ws[wrow][wq * 4 + 0] = wa.x; Ws[wrow][wq * 4 + 1] = wa.y;
        Ws[wrow][wq * 4 + 2] = wa.z; Ws[wrow][wq * 4 + 3] = wa.w;
        Ws[wrow][(wq + 16) * 4 + 0] = wb.x; Ws[wrow][(wq + 16) * 4 + 1] = wb.y;
        Ws[wrow][(wq + 16) * 4 + 2] = wb.z; Ws[wrow][(wq + 16) * 4 + 3] = wb.w;
        Xs[xq * 4 + 0][xrow] = xr.x;
        Xs[xq * 4 + 1][xrow] = xr.y;
        Xs[xq * 4 + 2][xrow] = xr.z;
        Xs[xq * 4 + 3][xrow] = xr.w;
        __syncthreads();

        // prefetch next tile (overlaps with compute below)
        if (kt + 1 < NKT) {
            const int k0n = (kt + 1) * BK;
            const float* wp = Wg + ((size_t)k0n + wrow) * H_N;
            wa = *(const float4*)(wp + wq * 4);
            wb = *(const float4*)(wp + (wq + 16) * 4);
            const float* xp = xs + (size_t)srow[xrow] * D_N + k0n + xq * 4;
            xr = *(const float4*)xp;
        }

#pragma unroll
        for (int kk = 0; kk < BK; kk++) {
            unsigned long long w0 = *(const unsigned long long*)&Ws[kk][tx * 4];
            unsigned long long w1 = *(const unsigned long long*)&Ws[kk][tx * 4 + 2];
#pragma unroll
            for (int i = 0; i < 8; i++) {
                float xv = Xs[kk][ty + i * 8];
                unsigned long long xp2 = pack2(xv, xv);
                acc[i][0] = fma_f32x2(xp2, w0, acc[i][0]);
                acc[i][1] = fma_f32x2(xp2, w1, acc[i][1]);
            }
        }
        __syncthreads();
    }

    // epilogue: bias + relu, store to g_h (sorted order), coalesced float4
    const float4 bv = *(const float4*)&b1[(size_t)t * H_N + cBase + tx * 4];
#pragma unroll
    for (int i = 0; i < 8; i++) {
        int r = ty + i * 8;
        int p = rowStart + r;
        if (p < end) {
            float2 lo = unpack2(acc[i][0]);
            float2 hi = unpack2(acc[i][1]);
            float4 o;
            o.x = fmaxf(lo.x + bv.x, 0.f);
            o.y = fmaxf(lo.y + bv.y, 0.f);
            o.z = fmaxf(hi.x + bv.z, 0.f);
            o.w = fmaxf(hi.y + bv.w, 0.f);
            *(float4*)&g_h[(size_t)p * H_N + cBase + tx * 4] = o;
        }
    }
}

// ---------------- kernel 3: fc2 logits + log_softmax + entropy ----------------
// 32 rows/block (same task), W2^T staged in smem, one warp -> 4 rows.
// Lane a (<18) computes logit_a; warp shuffles do softmax reductions.
__global__ __launch_bounds__(256)
void head_kernel(const float* __restrict__ W2,
                 const float* __restrict__ b2,
                 const int* __restrict__ action,
                 float* __restrict__ out) {
    const int t = blockIdx.y;
    const int start = g_offsets[t] + blockIdx.x * 32;
    const int end   = g_offsets[t + 1];
    if (start >= end) return;

    __shared__ float w2s[A_N][H_N];   // transposed: [a][h], 36 KB
    __shared__ float b2s[A_N];

    const int tid = threadIdx.x;
    for (int idx = tid; idx < H_N * A_N; idx += blockDim.x) {
        int hh = idx / A_N;
        int a  = idx - hh * A_N;
        w2s[a][hh] = W2[((size_t)t * H_N + hh) * A_N + a];
    }
    if (tid < A_N) b2s[tid] = b2[t * A_N + tid];
    __syncthreads();

    const int warp = tid >> 5;
    const int lane = tid & 31;
    const bool act = lane < A_N;
    const int aa = act ? lane : 0;
    const float NEG_INF = __int_as_float(0xff800000);

    for (int rr = 0; rr < 4; rr++) {
        int p = start + warp * 4 + rr;
        if (p >= end) break;
        const float* hrow = &g_h[(size_t)p * H_N];
        const float* wr = &w2s[aa][0];
        float accv = 0.f;
#pragma unroll 4
        for (int j = 0; j < H_N / 4; j++) {
            float4 hv = *(const float4*)(hrow + j * 4);   // broadcast across lanes
            float4 wv = *(const float4*)(wr + j * 4);
            accv = fmaf(hv.x, wv.x, accv);
            accv = fmaf(hv.y, wv.y, accv);
            accv = fmaf(hv.z, wv.z, accv);
            accv = fmaf(hv.w, wv.w, accv);
        }
        float logit = accv + b2s[aa];
        float lg = act ? logit : NEG_INF;
        // warp max
        float m = lg;
#pragma unroll
        for (int o = 16; o > 0; o >>= 1)
            m = fmaxf(m, __shfl_xor_sync(0xffffffffu, m, o));
        float e = act ? expf(logit - m) : 0.f;
        float v = act ? e * (logit - m) : 0.f;
        float S1 = e, S2 = v;
#pragma unroll
        for (int o = 16; o > 0; o >>= 1) {
            S1 += __shfl_xor_sync(0xffffffffu, S1, o);
            S2 += __shfl_xor_sync(0xffffffffu, S2, o);
        }
        float logS = logf(S1);
        float logp = logit - m - logS;          // valid where act
        float ent  = logS - S2 / S1;

        int orig = g_rowmap[p];
        int a_star = action[orig];
        if (lane == a_star) out[B_N + orig] = logp;
        if (lane == 0) {
            out[orig]         = (float)a_star;
            out[2 * B_N + orig] = ent;
        }
    }
}

// ---------------- launch ----------------
extern "C" void kernel_launch(void* const* d_in, const int* in_sizes, int n_in,
                              void* d_out, int out_size) {
    (void)in_sizes; (void)n_in; (void)out_size;
    const float* xs   = (const float*)d_in[0];
    const float* W1   = (const float*)d_in[1];
    const float* b1   = (const float*)d_in[2];
    const float* W2   = (const float*)d_in[3];
    const float* b2   = (const float*)d_in[4];
    const int*   task = (const int*)d_in[5];
    const int*   act  = (const int*)d_in[6];
    float* out = (float*)d_out;

    group_kernel<<<1, 1024>>>(task);
    // grid.x covers worst-case task occupancy (all rows one task)
    fc1_kernel<<<dim3(B_N / BM, H_N / BN, T_N), 256>>>(xs, W1, b1);
    head_kernel<<<dim3(B_N / 32, T_N), 256>>>(W2, b2, act, out);
}

// round 3
// speedup vs baseline: 2.4968x; 2.4968x over previous
#include <cuda_runtime.h>
#include <cuda_bf16.h>
#include <math.h>
#include <stdint.h>

// Problem constants (fixed shapes)
#define B_N 2048
#define D_N 512
#define H_N 512
#define A_N 18
#define T_N 16

#define BM 64
#define BN 128
#define BK 16
#define NPART (H_N / BN)   // 4 column blocks = 4 K-chunks for fc2 partials

// ---------------- device scratch (no allocation allowed) ----------------
__device__ int   g_offsets[T_N + 1];
__device__ int   g_rowmap[B_N];                       // sorted-by-task original row idx
__device__ int   g_taskof[B_N];                       // task of sorted slot p
__device__ float g_lpart[NPART][B_N][A_N];            // fc2 partial logits (~590KB)

// ---------------- f32x2 helpers (packed fp32, 2 MACs/instr) ----------------
__device__ __forceinline__ unsigned long long fma_f32x2(unsigned long long a,
                                                        unsigned long long b,
                                                        unsigned long long c) {
    unsigned long long d;
    asm("fma.rn.f32x2 %0, %1, %2, %3;" : "=l"(d) : "l"(a), "l"(b), "l"(c));
    return d;
}
__device__ __forceinline__ unsigned long long pack2(float x, float y) {
    unsigned long long r;
    asm("mov.b64 %0, {%1, %2};" : "=l"(r) : "f"(x), "f"(y));
    return r;
}
__device__ __forceinline__ float2 unpack2(unsigned long long v) {
    float2 r;
    asm("mov.b64 {%0, %1}, %2;" : "=f"(r.x), "=f"(r.y) : "l"(v));
    return r;
}

// ---------------- kernel 1: group rows by task (warp-aggregated atomics) ----
__global__ void group_kernel(const int* __restrict__ task_id) {
    __shared__ int scnt[T_N];
    __shared__ int soff[T_N + 1];
    __shared__ int scur[T_N];
    const int tid = threadIdx.x;
    const int lane = tid & 31;
    if (tid < T_N) { scnt[tid] = 0; scur[tid] = 0; }
    __syncthreads();

#pragma unroll
    for (int it = 0; it < B_N / 1024; it++) {
        int b = it * 1024 + tid;
        int t = task_id[b];
        unsigned m = __match_any_sync(0xffffffffu, t);
        int leader = __ffs(m) - 1;
        if (lane == leader) atomicAdd(&scnt[t], __popc(m));
    }
    __syncthreads();
    if (tid == 0) {
        int acc = 0;
        for (int t = 0; t < T_N; t++) { soff[t] = acc; acc += scnt[t]; }
        soff[T_N] = acc;
    }
    __syncthreads();
    if (tid <= T_N) g_offsets[tid] = soff[tid];

#pragma unroll
    for (int it = 0; it < B_N / 1024; it++) {
        int b = it * 1024 + tid;
        int t = task_id[b];
        unsigned m = __match_any_sync(0xffffffffu, t);
        int leader = __ffs(m) - 1;
        int rank = __popc(m & ((1u << lane) - 1u));
        int base = 0;
        if (lane == leader) base = atomicAdd(&scur[t], __popc(m));
        base = __shfl_sync(m, base, leader);
        int p = soff[t] + base + rank;
        g_rowmap[p] = b;
        g_taskof[p] = t;
    }
}

// ---------------- kernel 2: fused fc1 GEMM + bias + relu + fc2 partials -----
// Tile 64x128, BK=16, 256 threads. Thread tile: 8 consecutive rows x 4 cols,
// accumulated as f32x2 row-pairs. Epilogue multiplies the h tile by the
// matching 128x18 W2 slice and writes partial logits (no atomics).
__global__ __launch_bounds__(256, 2)
void fc1_kernel(const float* __restrict__ xs,
                const float* __restrict__ W1,
                const float* __restrict__ b1,
                const float* __restrict__ W2) {
    const int t = blockIdx.z;
    const int start = g_offsets[t];
    const int end   = g_offsets[t + 1];
    const int rowStart = start + blockIdx.x * BM;
    if (rowStart >= end) return;
    const int cb = blockIdx.y;
    const int cBase = cb * BN;

    __shared__ __align__(16) float Xs[BK][BM + 4];  // stride 68 (16B-aligned rows)
    __shared__ __align__(16) float Ws[BK][BN];
    __shared__ __align__(16) float Hs[BM][BN + 4];  // h tile, ROW-major, stride 132
    __shared__ int srow[BM];

    const int tid = threadIdx.x;
    const int tx = tid & 31;              // col group: cols tx*4..tx*4+3
    const int ty = tid >> 5;              // row group: rows ty*8..ty*8+7

    if (tid < BM) {
        int p = rowStart + tid;
        srow[tid] = g_rowmap[(p < end) ? p : rowStart];
    }
    __syncthreads();

    const int wrow = tid >> 4;            // 0..15
    const int wq   = tid & 15;
    const int xrow = tid >> 2;            // 0..63
    const int xq   = tid & 3;

    const float* __restrict__ Wg = W1 + ((size_t)t * D_N) * H_N + cBase;

    float4 wa, wb, xr;
    {
        const float* wp = Wg + (size_t)wrow * H_N;
        wa = *(const float4*)(wp + wq * 4);
        wb = *(const float4*)(wp + (wq + 16) * 4);
        const float* xp = xs + (size_t)srow[xrow] * D_N + xq * 4;
        xr = *(const float4*)xp;
    }

    unsigned long long acc[4][4];         // [row-pair u][col j]
    const unsigned long long z = pack2(0.f, 0.f);
#pragma unroll
    for (int u = 0; u < 4; u++)
#pragma unroll
        for (int j = 0; j < 4; j++) acc[u][j] = z;

    const int NKT = D_N / BK;             // 32
    for (int kt = 0; kt < NKT; kt++) {
        Ws[wrow][wq * 4 + 0] = wa.x; Ws[wrow][wq * 4 + 1] = wa.y;
        Ws[wrow][wq * 4 + 2] = wa.z; Ws[wrow][wq * 4 + 3] = wa.w;
        Ws[wrow][(wq + 16) * 4 + 0] = wb.x; Ws[wrow][(wq + 16) * 4 + 1] = wb.y;
        Ws[wrow][(wq + 16) * 4 + 2] = wb.z; Ws[wrow][(wq + 16) * 4 + 3] = wb.w;
        Xs[xq * 4 + 0][xrow] = xr.x;
        Xs[xq * 4 + 1][xrow] = xr.y;
        Xs[xq * 4 + 2][xrow] = xr.z;
        Xs[xq * 4 + 3][xrow] = xr.w;
        __syncthreads();

        if (kt + 1 < NKT) {
            const int k0n = (kt + 1) * BK;
            const float* wp = Wg + ((size_t)k0n + wrow) * H_N;
            wa = *(const float4*)(wp + wq * 4);
            wb = *(const float4*)(wp + (wq + 16) * 4);
            const float* xp = xs + (size_t)srow[xrow] * D_N + k0n + xq * 4;
            xr = *(const float4*)xp;
        }

#pragma unroll
        for (int kk = 0; kk < BK; kk++) {
            ulonglong2 xA = *(const ulonglong2*)&Xs[kk][ty * 8];      // rows 0-3
            ulonglong2 xB = *(const ulonglong2*)&Xs[kk][ty * 8 + 4];  // rows 4-7
            float4 wv = *(const float4*)&Ws[kk][tx * 4];
            unsigned long long w0 = pack2(wv.x, wv.x);
            unsigned long long w1 = pack2(wv.y, wv.y);
            unsigned long long w2 = pack2(wv.z, wv.z);
            unsigned long long w3 = pack2(wv.w, wv.w);
            acc[0][0] = fma_f32x2(xA.x, w0, acc[0][0]);
            acc[0][1] = fma_f32x2(xA.x, w1, acc[0][1]);
            acc[0][2] = fma_f32x2(xA.x, w2, acc[0][2]);
            acc[0][3] = fma_f32x2(xA.x, w3, acc[0][3]);
            acc[1][0] = fma_f32x2(xA.y, w0, acc[1][0]);
            acc[1][1] = fma_f32x2(xA.y, w1, acc[1][1]);
            acc[1][2] = fma_f32x2(xA.y, w2, acc[1][2]);
            acc[1][3] = fma_f32x2(xA.y, w3, acc[1][3]);
            acc[2][0] = fma_f32x2(xB.x, w0, acc[2][0]);
            acc[2][1] = fma_f32x2(xB.x, w1, acc[2][1]);
            acc[2][2] = fma_f32x2(xB.x, w2, acc[2][2]);
            acc[2][3] = fma_f32x2(xB.x, w3, acc[2][3]);
            acc[3][0] = fma_f32x2(xB.y, w0, acc[3][0]);
            acc[3][1] = fma_f32x2(xB.y, w1, acc[3][1]);
            acc[3][2] = fma_f32x2(xB.y, w2, acc[3][2]);
            acc[3][3] = fma_f32x2(xB.y, w3, acc[3][3]);
        }
        __syncthreads();
    }

    // epilogue: bias + relu -> Hs (row-major, conflict-free float4 stores)
    const float4 bv = *(const float4*)&b1[(size_t)t * H_N + cBase + tx * 4];
#pragma unroll
    for (int u = 0; u < 4; u++) {
        float2 p0 = unpack2(acc[u][0]);
        float2 p1 = unpack2(acc[u][1]);
        float2 p2 = unpack2(acc[u][2]);
        float2 p3 = unpack2(acc[u][3]);
        float4 r0, r1;
        r0.x = fmaxf(p0.x + bv.x, 0.f); r0.y = fmaxf(p1.x + bv.y, 0.f);
        r0.z = fmaxf(p2.x + bv.z, 0.f); r0.w = fmaxf(p3.x + bv.w, 0.f);
        r1.x = fmaxf(p0.y + bv.x, 0.f); r1.y = fmaxf(p1.y + bv.y, 0.f);
        r1.z = fmaxf(p2.y + bv.z, 0.f); r1.w = fmaxf(p3.y + bv.w, 0.f);
        *(float4*)&Hs[ty * 8 + 2 * u + 0][tx * 4] = r0;
        *(float4*)&Hs[ty * 8 + 2 * u + 1][tx * 4] = r1;
    }
    __syncthreads();

    // fc2 partial: warp ty handles rows ty*8..ty*8+7; lane a<18 computes
    // logit col a over this block's 128-wide h chunk.
    // Hs[row][k]: same address across lanes -> warp broadcast, no conflicts.
    // W2 reads: lanes hit 18 consecutive floats -> coalesced, L1-resident.
    const bool act = tx < A_N;
    float acc2[8];
#pragma unroll
    for (int u = 0; u < 8; u++) acc2[u] = 0.f;
    const float* __restrict__ w2p =
        W2 + ((size_t)t * H_N + cBase) * A_N + (act ? tx : 0);
#pragma unroll 4
    for (int k = 0; k < BN; k++) {
        float wv = w2p[(size_t)k * A_N];
#pragma unroll
        for (int u = 0; u < 8; u++)
            acc2[u] = fmaf(Hs[ty * 8 + u][k], wv, acc2[u]);
    }
#pragma unroll
    for (int u = 0; u < 8; u++) {
        int p = rowStart + ty * 8 + u;
        if (p < end && act) g_lpart[cb][p][tx] = acc2[u];
    }
}

// ---------------- kernel 3: sum partials + bias + log_softmax + entropy -----
__global__ __launch_bounds__(256)
void head_kernel(const float* __restrict__ b2,
                 const int* __restrict__ action,
                 float* __restrict__ out) {
    const int tid = threadIdx.x;
    const int warp = tid >> 5;
    const int lane = tid & 31;
    const int p = blockIdx.x * 8 + warp;   // grid.x = B_N/8 exactly

    const int t = g_taskof[p];
    const int orig = g_rowmap[p];
    const bool act = lane < A_N;
    const int a = act ? lane : 0;

    float logit = b2[t * A_N + a];
#pragma unroll
    for (int cb = 0; cb < NPART; cb++) logit += g_lpart[cb][p][a];

    const float NEG_INF = __int_as_float(0xff800000);
    float lg = act ? logit : NEG_INF;
    float m = lg;
#pragma unroll
    for (int o = 16; o > 0; o >>= 1)
        m = fmaxf(m, __shfl_xor_sync(0xffffffffu, m, o));
    float e = act ? expf(logit - m) : 0.f;
    float v = act ? e * (logit - m) : 0.f;
    float S1 = e, S2 = v;
#pragma unroll
    for (int o = 16; o > 0; o >>= 1) {
        S1 += __shfl_xor_sync(0xffffffffu, S1, o);
        S2 += __shfl_xor_sync(0xffffffffu, S2, o);
    }
    float logS = logf(S1);
    float logp = logit - m - logS;
    float ent  = logS - S2 / S1;

    int a_star = action[orig];
    if (lane == a_star) out[B_N + orig] = logp;
    if (lane == 0) {
        out[orig]           = (float)a_star;
        out[2 * B_N + orig] = ent;
    }
}

// ---------------- launch ----------------
extern "C" void kernel_launch(void* const* d_in, const int* in_sizes, int n_in,
                              void* d_out, int out_size) {
    (void)in_sizes; (void)n_in; (void)out_size;
    const float* xs   = (const float*)d_in[0];
    const float* W1   = (const float*)d_in[1];
    const float* b1   = (const float*)d_in[2];
    const float* W2   = (const float*)d_in[3];
    const float* b2   = (const float*)d_in[4];
    const int*   task = (const int*)d_in[5];
    const int*   act  = (const int*)d_in[6];
    float* out = (float*)d_out;

    group_kernel<<<1, 1024>>>(task);
    fc1_kernel<<<dim3(B_N / BM, NPART, T_N), 256>>>(xs, W1, b1, W2);
    head_kernel<<<B_N / 8, 256>>>(b2, act, out);
}

// round 4
// speedup vs baseline: 2.4989x; 1.0009x over previous
#include <cuda_runtime.h>
#include <math.h>
#include <stdint.h>

// Problem constants (fixed shapes)
#define B_N 2048
#define D_N 512
#define H_N 512
#define A_N 18
#define T_N 16

#define BM 128
#define BN 128
#define BK 16
#define NPART (H_N / BN)   // 4 column blocks = 4 partial chunks for fc2

// ---------------- device scratch (no allocation allowed) ----------------
__device__ int   g_offsets[T_N + 1];
__device__ int   g_rowmap[B_N];               // sorted-by-task original row idx
__device__ int   g_taskof[B_N];               // task of sorted slot p
__device__ float g_lpart[NPART][B_N][A_N];    // fc2 partial logits (~590KB)

// ---------------- tf32 mma helpers ----------------
__device__ __forceinline__ uint32_t cvt_tf32(float x) {
    uint32_t r;
    asm("cvt.rna.tf32.f32 %0, %1;" : "=r"(r) : "f"(x));
    return r;
}
__device__ __forceinline__ void mma_tf32(float* c, const uint32_t* a, const uint32_t* b) {
    asm("mma.sync.aligned.m16n8k8.row.col.f32.tf32.tf32.f32 "
        "{%0,%1,%2,%3},{%4,%5,%6,%7},{%8,%9},{%0,%1,%2,%3};"
        : "+f"(c[0]), "+f"(c[1]), "+f"(c[2]), "+f"(c[3])
        : "r"(a[0]), "r"(a[1]), "r"(a[2]), "r"(a[3]), "r"(b[0]), "r"(b[1]));
}

// ---------------- kernel 1: group rows by task (atomic-free scan) ----------
// 1024 threads, each owns elements tid and tid+1024. Chunk = warp (64 chunks
// of 32). Per-chunk histograms via match_any, Hillis-Steele scan over the
// chunk dim, deterministic scatter. No atomics at all.
__global__ void group_kernel(const int* __restrict__ task_id) {
    __shared__ int hist[64][T_N];
    __shared__ int base[64][T_N];
    __shared__ int soff[T_N + 1];
    const int tid = threadIdx.x;
    const int lane = tid & 31;
    const int w = tid >> 5;                 // 0..31

    ((int*)hist)[tid] = 0;
    __syncthreads();

    const int e0 = tid, e1 = tid + 1024;
    int t0 = task_id[e0];
    unsigned m0 = __match_any_sync(0xffffffffu, t0);
    int r0 = __popc(m0 & ((1u << lane) - 1u));
    if (r0 == 0) hist[w][t0] = __popc(m0);
    int t1 = task_id[e1];
    unsigned m1 = __match_any_sync(0xffffffffu, t1);
    int r1 = __popc(m1 & ((1u << lane) - 1u));
    if (r1 == 0) hist[32 + w][t1] = __popc(m1);
    __syncthreads();

    // inclusive scan over chunk dim (64) per task column (16)
    const int c = tid >> 4, tt = tid & 15;
    int own = hist[c][tt];
    int v = own;
#pragma unroll
    for (int d = 1; d < 64; d <<= 1) {
        int add = (c >= d) ? hist[c - d][tt] : 0;
        __syncthreads();
        v += add;
        hist[c][tt] = v;
        __syncthreads();
    }
    if (tid == 0) {
        int acc = 0;
        for (int t = 0; t < T_N; t++) { soff[t] = acc; acc += hist[63][t]; }
        soff[T_N] = acc;
    }
    __syncthreads();
    base[c][tt] = soff[tt] + v - own;       // exclusive base for chunk c, task tt
    if (tid <= T_N) g_offsets[tid] = soff[tid];
    __syncthreads();

    int p0 = base[w][t0] + r0;
    g_rowmap[p0] = e0; g_taskof[p0] = t0;
    int p1 = base[32 + w][t1] + r1;
    g_rowmap[p1] = e1; g_taskof[p1] = t1;
}

// ---------------- kernel 2: tf32-MMA fc1 + bias + relu + fc2 partials ------
union SmemU {
    struct {
        float Xs[BM][BK + 4];   // stride 20: conflict-free A-frag LDS
        float Ws[BK][BN + 8];   // stride 136: conflict-free B-frag LDS
    } a;
    float Hs[64][BN + 4];       // h half-tile for fc2 partial (stride 132)
};

__global__ __launch_bounds__(256)
void fc1_kernel(const float* __restrict__ xs,
                const float* __restrict__ W1,
                const float* __restrict__ b1,
                const float* __restrict__ W2) {
    const int t = blockIdx.z;
    const int start = g_offsets[t];
    const int end   = g_offsets[t + 1];
    const int rowStart = start + blockIdx.x * BM;
    if (rowStart >= end) return;
    const int cb = blockIdx.y;
    const int cBase = cb * BN;

    __shared__ SmemU sm;
    __shared__ int   srow[BM];
    __shared__ float sb1[BN];

    const int tid  = threadIdx.x;
    const int lane = tid & 31;
    const int warp = tid >> 5;
    const int warp_m = warp >> 1;           // 0..3 -> rows warp_m*32
    const int warp_n = warp & 1;            // 0..1 -> cols warp_n*64
    const int g  = lane >> 2;               // groupID 0..7
    const int tg = lane & 3;                // thread-in-group 0..3

    if (tid < BM) {
        int p = rowStart + tid;
        srow[tid] = g_rowmap[(p < end) ? p : rowStart];
    }
    if (tid < BN) sb1[tid] = b1[(size_t)t * H_N + cBase + tid];
    __syncthreads();

    const int wrow = tid >> 4;              // 0..15
    const int wq   = tid & 15;
    const int xrow = tid >> 1;              // 0..127
    const int xq   = tid & 1;
    const float* __restrict__ Wg = W1 + ((size_t)t * D_N) * H_N + cBase;
    const float* __restrict__ xb = xs + (size_t)srow[xrow] * D_N;

    float4 wa, wb, xa, xv;
    {
        const float* wp = Wg + (size_t)wrow * H_N;
        wa = *(const float4*)(wp + wq * 4);
        wb = *(const float4*)(wp + (wq + 16) * 4);
        xa = *(const float4*)(xb + xq * 8);
        xv = *(const float4*)(xb + xq * 8 + 4);
    }

    float acc[2][8][4];
#pragma unroll
    for (int i = 0; i < 2; i++)
#pragma unroll
        for (int j = 0; j < 8; j++)
#pragma unroll
            for (int r = 0; r < 4; r++) acc[i][j][r] = 0.f;

    const int NKT = D_N / BK;               // 32
    for (int kt = 0; kt < NKT; kt++) {
        __syncthreads();
        *(float4*)&sm.a.Ws[wrow][wq * 4] = wa;
        *(float4*)&sm.a.Ws[wrow][(wq + 16) * 4] = wb;
        *(float4*)&sm.a.Xs[xrow][xq * 8] = xa;
        *(float4*)&sm.a.Xs[xrow][xq * 8 + 4] = xv;
        __syncthreads();

        if (kt + 1 < NKT) {
            const int k0n = (kt + 1) * BK;
            const float* wp = Wg + ((size_t)k0n + wrow) * H_N;
            wa = *(const float4*)(wp + wq * 4);
            wb = *(const float4*)(wp + (wq + 16) * 4);
            xa = *(const float4*)(xb + k0n + xq * 8);
            xv = *(const float4*)(xb + k0n + xq * 8 + 4);
        }

#pragma unroll
        for (int s = 0; s < 2; s++) {
            const int k0 = s * 8;
            uint32_t bf[8][2];
            const int br0 = k0 + tg, br1 = k0 + tg + 4;
#pragma unroll
            for (int wn = 0; wn < 8; wn++) {
                const int nc = warp_n * 64 + wn * 8 + g;
                bf[wn][0] = cvt_tf32(sm.a.Ws[br0][nc]);
                bf[wn][1] = cvt_tf32(sm.a.Ws[br1][nc]);
            }
#pragma unroll
            for (int wm = 0; wm < 2; wm++) {
                const int r = warp_m * 32 + wm * 16 + g;
                uint32_t af[4];
                af[0] = cvt_tf32(sm.a.Xs[r][k0 + tg]);
                af[1] = cvt_tf32(sm.a.Xs[r + 8][k0 + tg]);
                af[2] = cvt_tf32(sm.a.Xs[r][k0 + tg + 4]);
                af[3] = cvt_tf32(sm.a.Xs[r + 8][k0 + tg + 4]);
#pragma unroll
                for (int wn = 0; wn < 8; wn++)
                    mma_tf32(acc[wm][wn], af, bf[wn]);
            }
        }
    }

    // ---- epilogue in two 64-row halves (Hs aliases the load tiles) ----
    const bool actv = lane < A_N;
    const float* __restrict__ w2p =
        W2 + ((size_t)t * H_N + cBase) * A_N + (actv ? lane : 0);

#pragma unroll
    for (int half = 0; half < 2; half++) {
        __syncthreads();
        if ((warp_m >> 1) == half) {
            const int rbase = (warp_m & 1) * 32;
#pragma unroll
            for (int wm = 0; wm < 2; wm++) {
#pragma unroll
                for (int wn = 0; wn < 8; wn++) {
                    const int row = rbase + wm * 16 + g;
                    const int col = warp_n * 64 + wn * 8 + tg * 2;
                    const float b0 = sb1[col], b1v = sb1[col + 1];
                    sm.Hs[row][col]         = fmaxf(acc[wm][wn][0] + b0, 0.f);
                    sm.Hs[row][col + 1]     = fmaxf(acc[wm][wn][1] + b1v, 0.f);
                    sm.Hs[row + 8][col]     = fmaxf(acc[wm][wn][2] + b0, 0.f);
                    sm.Hs[row + 8][col + 1] = fmaxf(acc[wm][wn][3] + b1v, 0.f);
                }
            }
        }
        __syncthreads();

        // fc2 partial: warp handles 8 rows of this half; lane a<18 -> logit a
        float acc2[8];
#pragma unroll
        for (int u = 0; u < 8; u++) acc2[u] = 0.f;
#pragma unroll 4
        for (int k = 0; k < BN; k++) {
            const float wv = w2p[(size_t)k * A_N];
#pragma unroll
            for (int u = 0; u < 8; u++)
                acc2[u] = fmaf(sm.Hs[warp * 8 + u][k], wv, acc2[u]);
        }
#pragma unroll
        for (int u = 0; u < 8; u++) {
            const int p = rowStart + half * 64 + warp * 8 + u;
            if (p < end && actv) g_lpart[cb][p][lane] = acc2[u];
        }
    }
}

// ---------------- kernel 3: sum partials + bias + log_softmax + entropy ----
__global__ __launch_bounds__(256)
void head_kernel(const float* __restrict__ b2,
                 const int* __restrict__ action,
                 float* __restrict__ out) {
    const int tid = threadIdx.x;
    const int warp = tid >> 5;
    const int lane = tid & 31;
    const int p = blockIdx.x * 8 + warp;    // grid.x = B_N/8 exactly

    const int t = g_taskof[p];
    const int orig = g_rowmap[p];
    const bool act = lane < A_N;
    const int a = act ? lane : 0;

    float logit = b2[t * A_N + a];
#pragma unroll
    for (int cb = 0; cb < NPART; cb++) logit += g_lpart[cb][p][a];

    const float NEG_INF = __int_as_float(0xff800000);
    float lg = act ? logit : NEG_INF;
    float m = lg;
#pragma unroll
    for (int o = 16; o > 0; o >>= 1)
        m = fmaxf(m, __shfl_xor_sync(0xffffffffu, m, o));
    float e = act ? expf(logit - m) : 0.f;
    float v = act ? e * (logit - m) : 0.f;
    float S1 = e, S2 = v;
#pragma unroll
    for (int o = 16; o > 0; o >>= 1) {
        S1 += __shfl_xor_sync(0xffffffffu, S1, o);
        S2 += __shfl_xor_sync(0xffffffffu, S2, o);
    }
    float logS = logf(S1);
    float logp = logit - m - logS;
    float ent  = logS - S2 / S1;

    int a_star = action[orig];
    if (lane == a_star) out[B_N + orig] = logp;
    if (lane == 0) {
        out[orig]           = (float)a_star;
        out[2 * B_N + orig] = ent;
    }
}

// ---------------- launch ----------------
extern "C" void kernel_launch(void* const* d_in, const int* in_sizes, int n_in,
                              void* d_out, int out_size) {
    (void)in_sizes; (void)n_in; (void)out_size;
    const float* xs   = (const float*)d_in[0];
    const float* W1   = (const float*)d_in[1];
    const float* b1   = (const float*)d_in[2];
    const float* W2   = (const float*)d_in[3];
    const float* b2   = (const float*)d_in[4];
    const int*   task = (const int*)d_in[5];
    const int*   act  = (const int*)d_in[6];
    float* out = (float*)d_out;

    group_kernel<<<1, 1024>>>(task);
    fc1_kernel<<<dim3(B_N / BM, NPART, T_N), 256>>>(xs, W1, b1, W2);
    head_kernel<<<B_N / 8, 256>>>(b2, act, out);
}

// round 7
// speedup vs baseline: 3.9545x; 1.5825x over previous
#include <cuda_runtime.h>
#include <math.h>
#include <stdint.h>

// Problem constants (fixed shapes)
#define B_N 2048
#define D_N 512
#define H_N 512
#define A_N 18
#define T_N 16

#define BM 128
#define BN 128
#define BK 16
#define NPART (H_N / BN)   // 4 column blocks
#define NBLK 128           // grid for main kernel (>= max work items 124)

// ---------------- device scratch (no allocation allowed) ----------------
__device__ int   g_rowmap[B_N];
__device__ int   g_taskof[B_N];
__device__ float g_lpart[NPART][B_N][A_N];

// ---------------- tf32 mma helpers ----------------
__device__ __forceinline__ uint32_t cvt_tf32(float x) {
    uint32_t r;
    asm("cvt.rna.tf32.f32 %0, %1;" : "=r"(r) : "f"(x));
    return r;
}
__device__ __forceinline__ void mma_tf32(float* c, const uint32_t* a, const uint32_t* b) {
    asm("mma.sync.aligned.m16n8k8.row.col.f32.tf32.tf32.f32 "
        "{%0,%1,%2,%3},{%4,%5,%6,%7},{%8,%9},{%0,%1,%2,%3};"
        : "+f"(c[0]), "+f"(c[1]), "+f"(c[2]), "+f"(c[3])
        : "r"(a[0]), "r"(a[1]), "r"(a[2]), "r"(a[3]), "r"(b[0]), "r"(b[1]));
}

// ---------------- shared memory (phase-aliased union) ----------------
union Smem {
    struct { int hist[64][T_N]; int rowmap[B_N]; } grp;        // 12.3 KB (phase A)
    struct { float Xs[BM][BK + 4]; float Ws[BK][BN + 8]; } a;  // 18.9 KB (GEMM)
    float Hs[64][BN + 4];                                      // 33.8 KB (epilogue)
};

// =========== kernel 1: grouping + tf32 GEMM + bias/relu + fc2 partials =====
__global__ __launch_bounds__(256)
void main_kernel(const float* __restrict__ xs,
                 const float* __restrict__ W1,
                 const float* __restrict__ b1,
                 const float* __restrict__ W2,
                 const int* __restrict__ task_id) {
    __shared__ Smem sm;
    __shared__ int   soff[T_N + 1];
    __shared__ int   s_totals[T_N];
    __shared__ int   srow[BM];
    __shared__ float sb1[BN];

    const int tid  = threadIdx.x;
    const int lane = tid & 31;
    const int warp = tid >> 5;             // 0..7
    const int b    = blockIdx.x;

    // ---------- Phase A: grouping (redundant per block, atomic-free) -------
    for (int i = tid; i < 64 * T_N; i += 256) ((int*)sm.grp.hist)[i] = 0;
    __syncthreads();

    int et[8], er[8];
#pragma unroll
    for (int it = 0; it < 8; it++) {
        const int chunk = it * 8 + warp;
        const int e = chunk * 32 + lane;
        const int t = task_id[e];
        unsigned m = __match_any_sync(0xffffffffu, t);
        int r = __popc(m & ((1u << lane) - 1u));
        et[it] = t; er[it] = r;
        if (r == 0) sm.grp.hist[chunk][t] = __popc(m);
    }
    __syncthreads();

    // per-task exclusive scan over 64 chunks: warp w handles tasks 2w, 2w+1
#pragma unroll
    for (int s = 0; s < 2; s++) {
        const int t = warp * 2 + s;
        int v0 = sm.grp.hist[lane][t];
        int v1 = sm.grp.hist[lane + 32][t];
        int s0 = v0;
#pragma unroll
        for (int o = 1; o < 32; o <<= 1) {
            int u = __shfl_up_sync(0xffffffffu, s0, o);
            if (lane >= o) s0 += u;
        }
        int tot0 = __shfl_sync(0xffffffffu, s0, 31);
        int s1 = v1;
#pragma unroll
        for (int o = 1; o < 32; o <<= 1) {
            int u = __shfl_up_sync(0xffffffffu, s1, o);
            if (lane >= o) s1 += u;
        }
        s1 += tot0;
        int tot1 = __shfl_sync(0xffffffffu, s1, 31);
        sm.grp.hist[lane][t]      = s0 - v0;   // exclusive
        sm.grp.hist[lane + 32][t] = s1 - v1;
        if (lane == 0) s_totals[t] = tot1;
    }
    __syncthreads();

    if (warp == 0) {
        int v = (lane < T_N) ? s_totals[lane] : 0;
        int sv = v;
#pragma unroll
        for (int o = 1; o < 32; o <<= 1) {
            int u = __shfl_up_sync(0xffffffffu, sv, o);
            if (lane >= o) sv += u;
        }
        if (lane <= T_N) soff[lane] = sv - v;  // exclusive
    }
    __syncthreads();

    // scatter: local rowmap; 8 designated blocks also publish to global
#pragma unroll
    for (int it = 0; it < 8; it++) {
        const int chunk = it * 8 + warp;
        const int e = chunk * 32 + lane;
        const int t = et[it];
        const int p = soff[t] + sm.grp.hist[chunk][t] + er[it];
        sm.grp.rowmap[p] = e;
        if (b == it) { g_rowmap[p] = e; g_taskof[p] = t; }
    }
    __syncthreads();

    // ---------- work-item mapping (<=124 items, 1 per block) ---------------
    int t_my = -1, j_my = 0, cb_my = 0, rowStart = 0, rowEnd = 0;
    {
        int acc = 0;
#pragma unroll
        for (int t = 0; t < T_N; t++) {
            const int cnt = soff[t + 1] - soff[t];
            const int nb = (cnt + BM - 1) / BM;
            const int n = nb * NPART;
            if (t_my < 0 && b < acc + n) {
                const int rem = b - acc;
                t_my = t; j_my = rem >> 2; cb_my = rem & 3;
            }
            acc += n;
        }
        if (t_my >= 0) {
            rowStart = soff[t_my] + j_my * BM;
            rowEnd   = soff[t_my + 1];
        }
    }
    if (t_my < 0) return;   // no barrier anymore -> early exit is safe

    if (tid < BM) {
        const int p = rowStart + tid;
        srow[tid] = sm.grp.rowmap[(p < rowEnd) ? p : rowStart];
    }
    if (tid < BN) sb1[tid] = b1[(size_t)t_my * H_N + cb_my * BN + tid];
    __syncthreads();   // after this, sm.grp is dead -> sm.a usable

    // ---------- Phase B: tf32 GEMM -----------------------------------------
    const int cBase = cb_my * BN;
    const int warp_m = warp >> 1;       // 0..3
    const int warp_n = warp & 1;        // 0..1
    const int g  = lane >> 2;
    const int tg = lane & 3;

    const int wrow = tid >> 4;
    const int wq   = tid & 15;
    const int xrow = tid >> 1;
    const int xq   = tid & 1;
    const float* __restrict__ Wg = W1 + ((size_t)t_my * D_N) * H_N + cBase;
    const float* __restrict__ xb = xs + (size_t)srow[xrow] * D_N;

    float4 wa, wb, xa, xv;
    {
        const float* wp = Wg + (size_t)wrow * H_N;
        wa = *(const float4*)(wp + wq * 4);
        wb = *(const float4*)(wp + (wq + 16) * 4);
        xa = *(const float4*)(xb + xq * 8);
        xv = *(const float4*)(xb + xq * 8 + 4);
    }

    float acc[2][8][4];
#pragma unroll
    for (int i = 0; i < 2; i++)
#pragma unroll
        for (int j = 0; j < 8; j++)
#pragma unroll
            for (int r = 0; r < 4; r++) acc[i][j][r] = 0.f;

    const int NKT = D_N / BK;
    for (int kt = 0; kt < NKT; kt++) {
        __syncthreads();
        *(float4*)&sm.a.Ws[wrow][wq * 4] = wa;
        *(float4*)&sm.a.Ws[wrow][(wq + 16) * 4] = wb;
        *(float4*)&sm.a.Xs[xrow][xq * 8] = xa;
        *(float4*)&sm.a.Xs[xrow][xq * 8 + 4] = xv;
        __syncthreads();

        if (kt + 1 < NKT) {
            const int k0n = (kt + 1) * BK;
            const float* wp = Wg + ((size_t)k0n + wrow) * H_N;
            wa = *(const float4*)(wp + wq * 4);
            wb = *(const float4*)(wp + (wq + 16) * 4);
            xa = *(const float4*)(xb + k0n + xq * 8);
            xv = *(const float4*)(xb + k0n + xq * 8 + 4);
        }

#pragma unroll
        for (int s = 0; s < 2; s++) {
            const int k0 = s * 8;
            uint32_t bf[8][2];
            const int br0 = k0 + tg, br1 = k0 + tg + 4;
#pragma unroll
            for (int wn = 0; wn < 8; wn++) {
                const int nc = warp_n * 64 + wn * 8 + g;
                bf[wn][0] = cvt_tf32(sm.a.Ws[br0][nc]);
                bf[wn][1] = cvt_tf32(sm.a.Ws[br1][nc]);
            }
#pragma unroll
            for (int wm = 0; wm < 2; wm++) {
                const int r = warp_m * 32 + wm * 16 + g;
                uint32_t af[4];
                af[0] = cvt_tf32(sm.a.Xs[r][k0 + tg]);
                af[1] = cvt_tf32(sm.a.Xs[r + 8][k0 + tg]);
                af[2] = cvt_tf32(sm.a.Xs[r][k0 + tg + 4]);
                af[3] = cvt_tf32(sm.a.Xs[r + 8][k0 + tg + 4]);
#pragma unroll
                for (int wn = 0; wn < 8; wn++)
                    mma_tf32(acc[wm][wn], af, bf[wn]);
            }
        }
    }

    // ---------- epilogue: bias/relu -> Hs halves -> fc2 partials -----------
    const bool actv = lane < A_N;
    const float* __restrict__ w2p =
        W2 + ((size_t)t_my * H_N + cBase) * A_N + (actv ? lane : 0);

#pragma unroll
    for (int half = 0; half < 2; half++) {
        __syncthreads();
        if ((warp_m >> 1) == half) {
            const int rbase = (warp_m & 1) * 32;
#pragma unroll
            for (int wm = 0; wm < 2; wm++) {
#pragma unroll
                for (int wn = 0; wn < 8; wn++) {
                    const int row = rbase + wm * 16 + g;
                    const int col = warp_n * 64 + wn * 8 + tg * 2;
                    const float c0 = sb1[col], c1 = sb1[col + 1];
                    sm.Hs[row][col]         = fmaxf(acc[wm][wn][0] + c0, 0.f);
                    sm.Hs[row][col + 1]     = fmaxf(acc[wm][wn][1] + c1, 0.f);
                    sm.Hs[row + 8][col]     = fmaxf(acc[wm][wn][2] + c0, 0.f);
                    sm.Hs[row + 8][col + 1] = fmaxf(acc[wm][wn][3] + c1, 0.f);
                }
            }
        }
        __syncthreads();

        float acc2[8];
#pragma unroll
        for (int u = 0; u < 8; u++) acc2[u] = 0.f;
#pragma unroll 4
        for (int k = 0; k < BN; k++) {
            const float wv = w2p[(size_t)k * A_N];
#pragma unroll
            for (int u = 0; u < 8; u++)
                acc2[u] = fmaf(sm.Hs[warp * 8 + u][k], wv, acc2[u]);
        }
#pragma unroll
        for (int u = 0; u < 8; u++) {
            const int p = rowStart + half * 64 + warp * 8 + u;
            if (p < rowEnd && actv) g_lpart[cb_my][p][lane] = acc2[u];
        }
    }
}

// =========== kernel 2: sum partials + bias + log_softmax + entropy =========
__global__ __launch_bounds__(256)
void head_kernel(const float* __restrict__ b2,
                 const int* __restrict__ action,
                 float* __restrict__ out) {
    const int tid = threadIdx.x;
    const int warp = tid >> 5;
    const int lane = tid & 31;
    const int p = blockIdx.x * 8 + warp;    // grid.x = B_N/8 = 256

    const int t = g_taskof[p];
    const int orig = g_rowmap[p];
    const bool act = lane < A_N;
    const int a = act ? lane : 0;

    float logit = b2[t * A_N + a];
#pragma unroll
    for (int cb = 0; cb < NPART; cb++) logit += g_lpart[cb][p][a];

    const float NEG_INF = __int_as_float(0xff800000);
    float lg = act ? logit : NEG_INF;
    float m = lg;
#pragma unroll
    for (int o = 16; o > 0; o >>= 1)
        m = fmaxf(m, __shfl_xor_sync(0xffffffffu, m, o));
    float e = act ? expf(logit - m) : 0.f;
    float v = act ? e * (logit - m) : 0.f;
    float S1 = e, S2 = v;
#pragma unroll
    for (int o = 16; o > 0; o >>= 1) {
        S1 += __shfl_xor_sync(0xffffffffu, S1, o);
        S2 += __shfl_xor_sync(0xffffffffu, S2, o);
    }
    float logS = logf(S1);
    float logp = logit - m - logS;
    float ent  = logS - S2 / S1;

    int a_star = action[orig];
    if (lane == a_star) out[B_N + orig] = logp;
    if (lane == 0) {
        out[orig]           = (float)a_star;
        out[2 * B_N + orig] = ent;
    }
}

// ---------------- launch ----------------
extern "C" void kernel_launch(void* const* d_in, const int* in_sizes, int n_in,
                              void* d_out, int out_size) {
    (void)in_sizes; (void)n_in; (void)out_size;
    const float* xs   = (const float*)d_in[0];
    const float* W1   = (const float*)d_in[1];
    const float* b1   = (const float*)d_in[2];
    const float* W2   = (const float*)d_in[3];
    const float* b2   = (const float*)d_in[4];
    const int*   task = (const int*)d_in[5];
    const int*   act  = (const int*)d_in[6];
    float* out = (float*)d_out;

    main_kernel<<<NBLK, 256>>>(xs, W1, b1, W2, task);
    head_kernel<<<B_N / 8, 256>>>(b2, act, out);
}